// round 11
// baseline (speedup 1.0000x reference)
#include <cuda_runtime.h>

// TorchSTFT collapses analytically to an elementwise scale (see R1):
//   out[b,t] = x[b,t] * COLA(t+400) * invnorm
// COLA == 1.5 exactly for t in [200, 159800) (periodic Hann, 75% overlap);
// explicit partial COLA sum on the ~400 edge samples per row.
//
// R10/R11: R6 shape (grid=1184 = one full wave on 148 SMs x 8 blocks, VPT=4 +
// conditional tail, loads batched) with __launch_bounds__(256, 8) forcing
// regs<=32 so the whole grid is truly resident in one wave. R9 proved the
// 9us wall is memory-path independent (LDG == TMA); the only residual lever
// is wave residency/ramp.

#define TIME      160000
#define BATCH     32
#define ROW_VEC   (TIME / 4)              // 40000 float4 per row
#define TOTAL_VEC (BATCH * ROW_VEC)       // 1,280,000
#define TPB       256
#define NBLOCKS   1184                    // 148 SMs * 8 blocks/SM
#define GSTRIDE   (NBLOCKS * TPB)         // 303,104 threads
#define VPT       4
// 4*GSTRIDE = 1,212,416 ; tail = 67,584 vectors -> threads [0, 67584)

// invnorm = sqrt(1 - 0.25 + 1e-8)
#define INVNORM_F 0.86602540956f
// interior gain = 1.5 * invnorm
#define CGAIN_F   1.29903811433f

// Exact partial COLA gain (float). Valid for all t; used only on edge vectors.
__device__ __forceinline__ float edge_gain(int t) {
    int p = t + 400;                          // OLA-coordinate position
    int fmin = (p > 799) ? (p - 799 + 199) / 200 : 0;
    int fmax = p / 200;
    if (fmax > 800) fmax = 800;               // F-1 = 800
    float s = 0.0f;
    for (int f = fmin; f <= fmax; ++f) {
        int n = p - 200 * f;                  // 0..799
        // hann_periodic(n) = 0.5 - 0.5*cospi(n/400)
        float w = 0.5f - 0.5f * cospif((float)n * (1.0f / 400.0f));
        s += w * w;
    }
    return s * INVNORM_F;
}

__device__ __forceinline__ void scale_vec(float4& v, unsigned idx) {
    unsigned row = idx / ROW_VEC;             // compiler -> mul-hi reciprocal
    int t0 = (int)(idx - row * ROW_VEC) * 4;  // element offset within row
    if (t0 >= 200 && t0 <= 159796) {          // whole vector in COLA interior
        v.x *= CGAIN_F;
        v.y *= CGAIN_F;
        v.z *= CGAIN_F;
        v.w *= CGAIN_F;
    } else {
        v.x *= edge_gain(t0);
        v.y *= edge_gain(t0 + 1);
        v.z *= edge_gain(t0 + 2);
        v.w *= edge_gain(t0 + 3);
    }
}

__global__ void __launch_bounds__(TPB, 8)     // force regs<=32: full residency
torchstft_scale_kernel(const float4* __restrict__ in, float4* __restrict__ out) {
    unsigned tid = blockIdx.x * TPB + threadIdx.x;

    // Batch all loads first: 4 (+1 conditional) independent LDG.128 in flight.
    float4 v[VPT];
#pragma unroll
    for (int k = 0; k < VPT; ++k)
        v[k] = in[tid + k * GSTRIDE];

    unsigned tail_idx = tid + VPT * GSTRIDE;
    bool has_tail = tail_idx < TOTAL_VEC;
    float4 vt;
    if (has_tail) vt = in[tail_idx];

#pragma unroll
    for (int k = 0; k < VPT; ++k) {
        unsigned idx = tid + k * GSTRIDE;
        scale_vec(v[k], idx);
        out[idx] = v[k];
    }
    if (has_tail) {
        scale_vec(vt, tail_idx);
        out[tail_idx] = vt;
    }
}

extern "C" void kernel_launch(void* const* d_in, const int* in_sizes, int n_in,
                              void* d_out, int out_size) {
    (void)in_sizes; (void)n_in; (void)out_size;
    const float4* in = (const float4*)d_in[0];
    float4* out = (float4*)d_out;
    torchstft_scale_kernel<<<NBLOCKS, TPB>>>(in, out);
}

// round 12
// speedup vs baseline: 1.0388x; 1.0388x over previous
#include <cuda_runtime.h>

// TorchSTFT collapses analytically to an elementwise scale (see R1):
//   out[b,t] = x[b,t] * COLA(t+400) * invnorm
// COLA == 1.5 exactly for t in [200, 159800) (periodic Hann, 75% overlap);
// explicit partial COLA sum on the ~400 edge samples per row.
//
// R12: R6 single-wave shape (grid=1184, VPT=4 + tail), but load batching
// split 2+3 to cut MLP_p1 from 5 to ~2. Evidence: duration tracks
// oe*MLP_p1 (cross-CTA L1tex-queue spread), not occupancy/path/waves:
//   R6 (oe~6,MLP5)=9.06, R4 (oe8,MLP4)=9.12, R5/R11 (oe*MLP>=40)=10.2+.
// Target oe*MLP_p1 <= ~16 (the spread-model knee).

#define TIME      160000
#define BATCH     32
#define ROW_VEC   (TIME / 4)              // 40000 float4 per row
#define TOTAL_VEC (BATCH * ROW_VEC)       // 1,280,000
#define TPB       256
#define NBLOCKS   1184                    // 148 SMs * 8 blocks/SM, one wave
#define GSTRIDE   (NBLOCKS * TPB)         // 303,104 threads
// vectors 0..3 at tid + k*GSTRIDE, plus conditional tail at tid + 4*GSTRIDE

// invnorm = sqrt(1 - 0.25 + 1e-8)
#define INVNORM_F 0.86602540956f
// interior gain = 1.5 * invnorm
#define CGAIN_F   1.29903811433f

// Exact partial COLA gain (float). Valid for all t; used only on edge vectors.
__device__ __forceinline__ float edge_gain(int t) {
    int p = t + 400;                          // OLA-coordinate position
    int fmin = (p > 799) ? (p - 799 + 199) / 200 : 0;
    int fmax = p / 200;
    if (fmax > 800) fmax = 800;               // F-1 = 800
    float s = 0.0f;
    for (int f = fmin; f <= fmax; ++f) {
        int n = p - 200 * f;                  // 0..799
        // hann_periodic(n) = 0.5 - 0.5*cospi(n/400)
        float w = 0.5f - 0.5f * cospif((float)n * (1.0f / 400.0f));
        s += w * w;
    }
    return s * INVNORM_F;
}

__device__ __forceinline__ void scale_vec(float4& v, unsigned idx) {
    unsigned row = idx / ROW_VEC;             // mul-hi reciprocal
    int t0 = (int)(idx - row * ROW_VEC) * 4;  // element offset within row
    if (t0 >= 200 && t0 <= 159796) {          // whole vector in COLA interior
        v.x *= CGAIN_F;
        v.y *= CGAIN_F;
        v.z *= CGAIN_F;
        v.w *= CGAIN_F;
    } else {
        v.x *= edge_gain(t0);
        v.y *= edge_gain(t0 + 1);
        v.z *= edge_gain(t0 + 2);
        v.w *= edge_gain(t0 + 3);
    }
}

__global__ void __launch_bounds__(TPB)
torchstft_scale_kernel(const float4* __restrict__ in, float4* __restrict__ out) {
    unsigned tid = blockIdx.x * TPB + threadIdx.x;

    // --- batch 1: vectors 0,1 (MLP_p1 = 2) ---
    float4 v0 = in[tid + 0u * GSTRIDE];
    float4 v1 = in[tid + 1u * GSTRIDE];
    scale_vec(v0, tid + 0u * GSTRIDE);
    out[tid + 0u * GSTRIDE] = v0;
    scale_vec(v1, tid + 1u * GSTRIDE);
    out[tid + 1u * GSTRIDE] = v1;

    // --- batch 2: vectors 2,3 + conditional tail ---
    unsigned tail_idx = tid + 4u * GSTRIDE;
    bool has_tail = tail_idx < TOTAL_VEC;
    float4 v2 = in[tid + 2u * GSTRIDE];
    float4 v3 = in[tid + 3u * GSTRIDE];
    float4 vt;
    if (has_tail) vt = in[tail_idx];

    scale_vec(v2, tid + 2u * GSTRIDE);
    out[tid + 2u * GSTRIDE] = v2;
    scale_vec(v3, tid + 3u * GSTRIDE);
    out[tid + 3u * GSTRIDE] = v3;
    if (has_tail) {
        scale_vec(vt, tail_idx);
        out[tail_idx] = vt;
    }
}

extern "C" void kernel_launch(void* const* d_in, const int* in_sizes, int n_in,
                              void* d_out, int out_size) {
    (void)in_sizes; (void)n_in; (void)out_size;
    const float4* in = (const float4*)d_in[0];
    float4* out = (float4*)d_out;
    torchstft_scale_kernel<<<NBLOCKS, TPB>>>(in, out);
}

// round 13
// speedup vs baseline: 1.1383x; 1.0957x over previous
#include <cuda_runtime.h>

// TorchSTFT collapses analytically to an elementwise scale (see R1):
//   out[b,t] = x[b,t] * COLA(t+400) * invnorm
// COLA == 1.5 exactly for t in [200, 159800) (periodic Hann, 75% overlap);
// explicit partial COLA sum on the ~400 edge samples per row.
//
// R13 == R6 (best measured: 9.056us). Confirmation run. Session evidence:
// seven structurally different kernels (LDG depth 1/4/8, split-batch,
// bulk-TMA, residency-forced) span 9.0-9.9us wall with every ncu counter
// at ~25% -> ~6.5us write-stream transfer + ~2.5-3us fixed replay/ramp.
// Single full-occupancy wave: 148 SMs x 8 blocks = 1184 blocks; each thread
// 4 front-batched vectors at stride G + 1 conditional tail vector.

#define TIME      160000
#define BATCH     32
#define ROW_VEC   (TIME / 4)              // 40000 float4 per row
#define TOTAL_VEC (BATCH * ROW_VEC)       // 1,280,000
#define TPB       256
#define NBLOCKS   1184                    // 148 SMs * 8 blocks/SM
#define GSTRIDE   (NBLOCKS * TPB)         // 303,104 threads
#define VPT       4
// 4*GSTRIDE = 1,212,416 ; tail = 67,584 vectors -> threads [0, 67584)

// invnorm = sqrt(1 - 0.25 + 1e-8)
#define INVNORM_F 0.86602540956f
// interior gain = 1.5 * invnorm
#define CGAIN_F   1.29903811433f

// Exact partial COLA gain (float). Valid for all t; used only on edge vectors.
__device__ __forceinline__ float edge_gain(int t) {
    int p = t + 400;                          // OLA-coordinate position
    int fmin = (p > 799) ? (p - 799 + 199) / 200 : 0;
    int fmax = p / 200;
    if (fmax > 800) fmax = 800;               // F-1 = 800
    float s = 0.0f;
    for (int f = fmin; f <= fmax; ++f) {
        int n = p - 200 * f;                  // 0..799
        // hann_periodic(n) = 0.5 - 0.5*cospi(n/400)
        float w = 0.5f - 0.5f * cospif((float)n * (1.0f / 400.0f));
        s += w * w;
    }
    return s * INVNORM_F;
}

__device__ __forceinline__ void scale_vec(float4& v, int idx) {
    int row = idx / ROW_VEC;
    int t0  = (idx - row * ROW_VEC) * 4;      // element offset within row
    if (t0 >= 200 && t0 <= 159796) {          // whole vector in COLA interior
        v.x *= CGAIN_F;
        v.y *= CGAIN_F;
        v.z *= CGAIN_F;
        v.w *= CGAIN_F;
    } else {
        v.x *= edge_gain(t0);
        v.y *= edge_gain(t0 + 1);
        v.z *= edge_gain(t0 + 2);
        v.w *= edge_gain(t0 + 3);
    }
}

__global__ void __launch_bounds__(TPB)
torchstft_scale_kernel(const float4* __restrict__ in, float4* __restrict__ out) {
    int tid = blockIdx.x * TPB + threadIdx.x;

    // Batch all loads first: 4 (+1 conditional) independent LDG.128 in flight.
    float4 v[VPT];
#pragma unroll
    for (int k = 0; k < VPT; ++k)
        v[k] = in[tid + k * GSTRIDE];

    int tail_idx = tid + VPT * GSTRIDE;
    bool has_tail = tail_idx < TOTAL_VEC;
    float4 vt;
    if (has_tail) vt = in[tail_idx];

#pragma unroll
    for (int k = 0; k < VPT; ++k) {
        int idx = tid + k * GSTRIDE;
        scale_vec(v[k], idx);
        out[idx] = v[k];
    }
    if (has_tail) {
        scale_vec(vt, tail_idx);
        out[tail_idx] = vt;
    }
}

extern "C" void kernel_launch(void* const* d_in, const int* in_sizes, int n_in,
                              void* d_out, int out_size) {
    (void)in_sizes; (void)n_in; (void)out_size;
    const float4* in = (const float4*)d_in[0];
    float4* out = (float4*)d_out;
    torchstft_scale_kernel<<<NBLOCKS, TPB>>>(in, out);
}